// round 5
// baseline (speedup 1.0000x reference)
#include <cuda_runtime.h>
#include <cuda_bf16.h>

#define N_NODES 50000
#define D_FEAT  128

// CSR row offsets into the sorted edge list. 50001 ints.
__device__ int g_offsets[N_NODES + 1];

// Kernel A: boundary-diff scatter. edge_src is sorted; thread e fills
// offsets[n] = e for all n in (edge_src[e-1], edge_src[e]].
__global__ void build_offsets_kernel(const int* __restrict__ edge_src, int n_edges) {
    int e = blockIdx.x * blockDim.x + threadIdx.x;
    if (e >= n_edges) return;
    int s1 = edge_src[e];
    int s0 = (e == 0) ? -1 : edge_src[e - 1];
    for (int n = s0 + 1; n <= s1; n++) g_offsets[n] = e;
    if (e == n_edges - 1) {
        for (int n = s1 + 1; n <= N_NODES; n++) g_offsets[n] = n_edges;
    }
}

// Kernel B: one warp per node, unroll-4 gathers (MLP=4: the measured sweet
// spot), with next iteration's indices software-pipelined so index-load
// latency overlaps the row gathers.
__global__ void __launch_bounds__(256)
graph_pool_kernel(const float4* __restrict__ x,
                  const int* __restrict__ edge_dst,
                  float4* __restrict__ out) {
    int warp_id = (blockIdx.x * blockDim.x + threadIdx.x) >> 5;
    int lane = threadIdx.x & 31;
    if (warp_id >= N_NODES) return;

    int beg = g_offsets[warp_id];
    int end = g_offsets[warp_id + 1];

    float4 acc0 = x[warp_id * 32 + lane];   // self feature
    float4 acc1 = make_float4(0.f, 0.f, 0.f, 0.f);

    int e = beg;
    int d0, d1, d2, d3;
    bool have = (e + 4 <= end);
    if (have) {
        d0 = edge_dst[e + 0];
        d1 = edge_dst[e + 1];
        d2 = edge_dst[e + 2];
        d3 = edge_dst[e + 3];
    }
    while (have) {
        int ne = e + 4;
        bool nhave = (ne + 4 <= end);
        int n0, n1, n2, n3;
        if (nhave) {                     // predicated preload, issues before gathers
            n0 = edge_dst[ne + 0];
            n1 = edge_dst[ne + 1];
            n2 = edge_dst[ne + 2];
            n3 = edge_dst[ne + 3];
        }
        float4 v0 = __ldg(&x[d0 * 32 + lane]);
        float4 v1 = __ldg(&x[d1 * 32 + lane]);
        float4 v2 = __ldg(&x[d2 * 32 + lane]);
        float4 v3 = __ldg(&x[d3 * 32 + lane]);
        acc0.x += v0.x; acc0.y += v0.y; acc0.z += v0.z; acc0.w += v0.w;
        acc1.x += v1.x; acc1.y += v1.y; acc1.z += v1.z; acc1.w += v1.w;
        acc0.x += v2.x; acc0.y += v2.y; acc0.z += v2.z; acc0.w += v2.w;
        acc1.x += v3.x; acc1.y += v3.y; acc1.z += v3.z; acc1.w += v3.w;
        e = ne;
        d0 = n0; d1 = n1; d2 = n2; d3 = n3;
        have = nhave;
    }
    for (; e < end; e++) {
        int d = edge_dst[e];
        float4 v = __ldg(&x[d * 32 + lane]);
        acc0.x += v.x; acc0.y += v.y; acc0.z += v.z; acc0.w += v.w;
    }

    acc0.x += acc1.x; acc0.y += acc1.y; acc0.z += acc1.z; acc0.w += acc1.w;
    out[warp_id * 32 + lane] = acc0;
}

extern "C" void kernel_launch(void* const* d_in, const int* in_sizes, int n_in,
                              void* d_out, int out_size) {
    const float* x = (const float*)d_in[0];
    const int* edge_src = (const int*)d_in[1];
    const int* edge_dst = (const int*)d_in[2];
    float* out = (float*)d_out;
    int n_edges = in_sizes[1];

    // Kernel A: O(E) boundary-diff offsets
    {
        int threads = 256;
        int blocks = (n_edges + threads - 1) / threads;
        build_offsets_kernel<<<blocks, threads>>>(edge_src, n_edges);
    }

    // Kernel B: one warp per node, 8 warps per block
    {
        int threads = 256;
        int warps_per_block = threads / 32;
        int blocks = (N_NODES + warps_per_block - 1) / warps_per_block;
        graph_pool_kernel<<<blocks, threads>>>((const float4*)x, edge_dst,
                                               (float4*)out);
    }
}

// round 6
// speedup vs baseline: 1.1561x; 1.1561x over previous
#include <cuda_runtime.h>
#include <cuda_bf16.h>

#define N_NODES 50000
#define D_FEAT  128

// CSR row offsets into the sorted edge list. 50001 ints.
__device__ int g_offsets[N_NODES + 1];

// Kernel A: boundary-diff scatter. edge_src is sorted; thread e fills
// offsets[n] = e for all n in (edge_src[e-1], edge_src[e]].
__global__ void build_offsets_kernel(const int* __restrict__ edge_src, int n_edges) {
    int e = blockIdx.x * blockDim.x + threadIdx.x;
    if (e >= n_edges) return;
    int s1 = edge_src[e];
    int s0 = (e == 0) ? -1 : edge_src[e - 1];
    for (int n = s0 + 1; n <= s1; n++) g_offsets[n] = e;
    if (e == n_edges - 1) {
        for (int n = s1 + 1; n <= N_NODES; n++) g_offsets[n] = n_edges;
    }
}

// Kernel B: one warp per node, plain unroll-4 (the measured optimum:
// regs=32, occ~82%). Broadcast index loads are L1-hot; 4 row gathers in
// flight; latency hidden by occupancy, not per-warp depth.
__global__ void __launch_bounds__(128)
graph_pool_kernel(const float4* __restrict__ x,
                  const int* __restrict__ edge_dst,
                  float4* __restrict__ out) {
    int warp_id = (blockIdx.x * blockDim.x + threadIdx.x) >> 5;
    int lane = threadIdx.x & 31;
    if (warp_id >= N_NODES) return;

    int beg = g_offsets[warp_id];
    int end = g_offsets[warp_id + 1];

    // self feature
    float4 acc = x[(size_t)warp_id * 32 + lane];

    int e = beg;
    for (; e + 4 <= end; e += 4) {
        int d0 = edge_dst[e + 0];
        int d1 = edge_dst[e + 1];
        int d2 = edge_dst[e + 2];
        int d3 = edge_dst[e + 3];
        float4 v0 = __ldg(&x[(size_t)d0 * 32 + lane]);
        float4 v1 = __ldg(&x[(size_t)d1 * 32 + lane]);
        float4 v2 = __ldg(&x[(size_t)d2 * 32 + lane]);
        float4 v3 = __ldg(&x[(size_t)d3 * 32 + lane]);
        acc.x += v0.x; acc.y += v0.y; acc.z += v0.z; acc.w += v0.w;
        acc.x += v1.x; acc.y += v1.y; acc.z += v1.z; acc.w += v1.w;
        acc.x += v2.x; acc.y += v2.y; acc.z += v2.z; acc.w += v2.w;
        acc.x += v3.x; acc.y += v3.y; acc.z += v3.z; acc.w += v3.w;
    }
    for (; e < end; e++) {
        int d = edge_dst[e];
        float4 v = __ldg(&x[(size_t)d * 32 + lane]);
        acc.x += v.x; acc.y += v.y; acc.z += v.z; acc.w += v.w;
    }

    out[(size_t)warp_id * 32 + lane] = acc;
}

extern "C" void kernel_launch(void* const* d_in, const int* in_sizes, int n_in,
                              void* d_out, int out_size) {
    const float* x = (const float*)d_in[0];
    const int* edge_src = (const int*)d_in[1];
    const int* edge_dst = (const int*)d_in[2];
    float* out = (float*)d_out;
    int n_edges = in_sizes[1];

    // Kernel A: O(E) boundary-diff offsets
    {
        int threads = 256;
        int blocks = (n_edges + threads - 1) / threads;
        build_offsets_kernel<<<blocks, threads>>>(edge_src, n_edges);
    }

    // Kernel B: one warp per node, 4 warps per block (fine-grained tail)
    {
        int threads = 128;
        int warps_per_block = threads / 32;
        int blocks = (N_NODES + warps_per_block - 1) / warps_per_block;
        graph_pool_kernel<<<blocks, threads>>>((const float4*)x, edge_dst,
                                               (float4*)out);
    }
}